// round 2
// baseline (speedup 1.0000x reference)
#include <cuda_runtime.h>
#include <cmath>

// ---------------------------------------------------------------------------
// SceneSegCNNTRM: fused pooling/cos-sim + conv-as-GEMM + banded transformer.
// Round 1: all-fp32 correctness baseline (tensor cores come next rounds).
//
// Shapes: B=4, N=1024, W=8, D=2048, H=256, COS_C=128, D_MODEL=640,
//         N_HEADS=8 (d_head=80), FF=128, N_LAYERS=6, M = B*N = 4096 tokens.
// ---------------------------------------------------------------------------

#define MROWS   4096
#define NB      1024          // tokens per batch (conv/attn boundary unit)
#define DIN     2048
#define DMODEL  640
#define NLAYER  6

// Scratch (static device globals -- no allocation allowed)
__device__ __align__(256) float g_pooled[MROWS * DIN];     // 33.5 MB
__device__ __align__(256) float g_out   [MROWS * DMODEL];  // feature / residual stream
__device__ __align__(256) float g_q     [MROWS * DMODEL];
__device__ __align__(256) float g_k     [MROWS * DMODEL];
__device__ __align__(256) float g_v     [MROWS * DMODEL];
__device__ __align__(256) float g_ctx   [MROWS * DMODEL];
__device__ __align__(256) float g_tmp   [MROWS * DMODEL];
__device__ __align__(256) float g_ff    [MROWS * 128];
__device__ __align__(256) float g_h     [MROWS * 256];

// ---------------------------------------------------------------------------
// Kernel 1: per (b,n) window -- 8x8 Gram matrix + row sums + attn-score dots
// in one pass over x; then cos-sim (quadratic forms) into g_out[:,512:640]
// and soft-attention pooled row into g_pooled.
// ---------------------------------------------------------------------------
__global__ __launch_bounds__(256) void pool_sim_kernel(
    const float* __restrict__ x,
    const float* __restrict__ cos_w, const float* __restrict__ cos_b,
    const float* __restrict__ attn_w, const float* __restrict__ attn_b,
    float* __restrict__ pooled, float* __restrict__ outbuf)
{
    const int m   = blockIdx.x;          // 0..4095
    const int tid = threadIdx.x;         // 256 threads
    const float* xr = x + (size_t)m * 8 * DIN;

    float g12[16], g11[10], g22[10], sw[8], ad[8];
#pragma unroll
    for (int i = 0; i < 16; i++) g12[i] = 0.f;
#pragma unroll
    for (int i = 0; i < 10; i++) { g11[i] = 0.f; g22[i] = 0.f; }
#pragma unroll
    for (int i = 0; i < 8; i++)  { sw[i] = 0.f; ad[i] = 0.f; }

    for (int d = tid; d < DIN; d += 256) {
        float xv[8];
#pragma unroll
        for (int w = 0; w < 8; w++) xv[w] = xr[w * DIN + d];
        const float aw = attn_w[d];
#pragma unroll
        for (int w = 0; w < 8; w++) { sw[w] += xv[w]; ad[w] += xv[w] * aw; }
#pragma unroll
        for (int i = 0; i < 4; i++)
#pragma unroll
            for (int j = 0; j < 4; j++)
                g12[i * 4 + j] += xv[i] * xv[4 + j];
#pragma unroll
        for (int i = 0; i < 4; i++)
#pragma unroll
            for (int j = i; j < 4; j++) {
                const int t = i * (7 - i) / 2 + j;  // triangular index
                g11[t] += xv[i] * xv[j];
                g22[t] += xv[4 + i] * xv[4 + j];
            }
    }

    // reduce 52 partials across the block: warp shuffle -> smem -> final
    __shared__ float red[52][8];
    __shared__ float fin[52];
    __shared__ float aprob[8];
    const int lane = tid & 31, wid = tid >> 5;

#define WREDUCE(arr, n, off)                                              \
    _Pragma("unroll")                                                     \
    for (int i = 0; i < n; i++) {                                         \
        float v = arr[i];                                                 \
        _Pragma("unroll")                                                 \
        for (int o = 16; o; o >>= 1) v += __shfl_xor_sync(0xffffffffu, v, o); \
        if (lane == 0) red[off + i][wid] = v;                             \
    }
    WREDUCE(g12, 16, 0)
    WREDUCE(g11, 10, 16)
    WREDUCE(g22, 10, 26)
    WREDUCE(sw,   8, 36)
    WREDUCE(ad,   8, 44)
#undef WREDUCE
    __syncthreads();
    if (tid < 52) {
        float t = 0.f;
#pragma unroll
        for (int w = 0; w < 8; w++) t += red[tid][w];
        fin[tid] = t;
    }
    __syncthreads();

    // soft-attention weights over the 8 window slots
    if (tid == 0) {
        const float ab = attn_b[0];
        float sc[8], mx = -1e30f;
#pragma unroll
        for (int w = 0; w < 8; w++) { sc[w] = fin[44 + w] + ab; mx = fmaxf(mx, sc[w]); }
        float s = 0.f;
#pragma unroll
        for (int w = 0; w < 8; w++) { sc[w] = expf(sc[w] - mx); s += sc[w]; }
        const float inv = 1.f / s;
#pragma unroll
        for (int w = 0; w < 8; w++) aprob[w] = sc[w] * inv;
    }

    // cos-sim channels: quadratic forms in the Gram blocks
    if (tid < 128) {
        float cw[4];
#pragma unroll
        for (int w = 0; w < 4; w++) cw[w] = cos_w[tid * 4 + w];
        const float cb = cos_b[tid];
        float d12 = 0.f, q1 = 0.f, q2 = 0.f, cs1 = 0.f, cs2 = 0.f;
#pragma unroll
        for (int i = 0; i < 4; i++)
#pragma unroll
            for (int j = 0; j < 4; j++)
                d12 += cw[i] * cw[j] * fin[i * 4 + j];
#pragma unroll
        for (int i = 0; i < 4; i++)
#pragma unroll
            for (int j = i; j < 4; j++) {
                const int t = i * (7 - i) / 2 + j;
                const float c2 = cw[i] * cw[j] * ((i == j) ? 1.f : 2.f);
                q1 += c2 * fin[16 + t];
                q2 += c2 * fin[26 + t];
            }
#pragma unroll
        for (int w = 0; w < 4; w++) {
            cs1 += cw[w] * fin[36 + w];
            cs2 += cw[w] * fin[40 + w];
        }
        d12 += cb * (cs1 + cs2) + (float)DIN * cb * cb;
        q1  += 2.f * cb * cs1 + (float)DIN * cb * cb;
        q2  += 2.f * cb * cs2 + (float)DIN * cb * cb;
        const float n1 = fmaxf(sqrtf(q1), 1e-8f);
        const float n2 = fmaxf(sqrtf(q2), 1e-8f);
        outbuf[(size_t)m * DMODEL + 512 + tid] = d12 / (n1 * n2);
    }
    __syncthreads();

    // pooled row (second read of x; row is L2-hot)
    float a[8];
#pragma unroll
    for (int w = 0; w < 8; w++) a[w] = aprob[w];
    for (int d = tid; d < DIN; d += 256) {
        float p = 0.f;
#pragma unroll
        for (int w = 0; w < 8; w++) p += a[w] * xr[w * DIN + d];
        pooled[(size_t)m * DIN + d] = p;
    }
}

// ---------------------------------------------------------------------------
// Generic fp32 SGEMM: C[M,N] (+)= A[M,K] * B[K,N], 128x128x8 tile, 8x8/thread.
//  - `shift`  : A row offset (conv tap), validity per batch of NB rows
//  - B strides (ldbK, ldbN) handle conv weight layout (Cout,Cin,3) directly
//  - flags: bit0 = relu, bit1 = accumulate into C
// M must be a multiple of 128, K a multiple of 8 (true for all call sites).
// ---------------------------------------------------------------------------
__global__ __launch_bounds__(256) void gemm128(
    const float* __restrict__ A, int lda, int shift,
    const float* __restrict__ B, int ldbK, int ldbN,
    const float* __restrict__ bias,
    float* __restrict__ C, int ldc,
    int M, int N, int K, int flags)
{
    __shared__ __align__(16) float As[8][128];
    __shared__ __align__(16) float Bs[8][128];

    const int bm  = blockIdx.y * 128;
    const int bn  = blockIdx.x * 128;
    const int tid = threadIdx.x;
    const int tx  = tid & 15;   // N-dim thread coord
    const int ty  = tid >> 4;   // M-dim thread coord

    float acc[8][8];
#pragma unroll
    for (int i = 0; i < 8; i++)
#pragma unroll
        for (int j = 0; j < 8; j++) acc[i][j] = 0.f;

    for (int k0 = 0; k0 < K; k0 += 8) {
        // --- load A tile (128 x 8), transposed into As[k][m], float4 loads
        {
            const int r  = tid >> 1;
            const int cg = (tid & 1) << 2;
            const int gm = bm + r;
            const int ar = gm + shift;
            float4 av = make_float4(0.f, 0.f, 0.f, 0.f);
            if ((unsigned)((gm & (NB - 1)) + shift) < (unsigned)NB)
                av = *reinterpret_cast<const float4*>(A + (size_t)ar * lda + k0 + cg);
            As[cg + 0][r] = av.x;
            As[cg + 1][r] = av.y;
            As[cg + 2][r] = av.z;
            As[cg + 3][r] = av.w;
        }
        // --- load B tile (8 x 128), generic strides
#pragma unroll
        for (int t = 0; t < 4; t++) {
            const int idx = tid + t * 256;
            const int kk  = idx >> 7;
            const int nn  = idx & 127;
            const int gn  = bn + nn;
            float v = 0.f;
            if (gn < N) v = B[(size_t)(k0 + kk) * ldbK + (size_t)gn * ldbN];
            Bs[kk][nn] = v;
        }
        __syncthreads();
#pragma unroll
        for (int kk = 0; kk < 8; kk++) {
            float a[8], b[8];
            *reinterpret_cast<float4*>(a)     = *reinterpret_cast<const float4*>(&As[kk][ty * 8]);
            *reinterpret_cast<float4*>(a + 4) = *reinterpret_cast<const float4*>(&As[kk][ty * 8 + 4]);
            *reinterpret_cast<float4*>(b)     = *reinterpret_cast<const float4*>(&Bs[kk][tx * 8]);
            *reinterpret_cast<float4*>(b + 4) = *reinterpret_cast<const float4*>(&Bs[kk][tx * 8 + 4]);
#pragma unroll
            for (int i = 0; i < 8; i++)
#pragma unroll
                for (int j = 0; j < 8; j++)
                    acc[i][j] = fmaf(a[i], b[j], acc[i][j]);
        }
        __syncthreads();
    }

    const int row0 = bm + ty * 8;
#pragma unroll
    for (int i = 0; i < 8; i++) {
        float* crow = C + (size_t)(row0 + i) * ldc;
#pragma unroll
        for (int j = 0; j < 8; j++) {
            const int gn = bn + tx * 8 + j;
            if (gn >= N) continue;
            float v = acc[i][j];
            if (bias) v += bias[gn];
            if (flags & 2) v += crow[gn];
            if (flags & 1) v = fmaxf(v, 0.f);
            crow[gn] = v;
        }
    }
}

// ---------------------------------------------------------------------------
// Banded local attention: each token attends to {i-1, i, i+1} within batch.
// One warp per (token, head); d_head = 80.
// ---------------------------------------------------------------------------
__global__ __launch_bounds__(256) void banded_attn_kernel(
    const float* __restrict__ q, const float* __restrict__ k,
    const float* __restrict__ v, float* __restrict__ ctx)
{
    const int gw   = (blockIdx.x * 256 + threadIdx.x) >> 5;
    const int lane = threadIdx.x & 31;
    if (gw >= MROWS * 8) return;
    const int m = gw >> 3;
    const int h = gw & 7;
    const int n = m & (NB - 1);
    const float scale = 0.11180339887498949f;  // 1/sqrt(80)

    const float* qp = q + (size_t)m * DMODEL + h * 80;
    float qv0 = qp[lane], qv1 = qp[lane + 32];
    float qv2 = (lane < 16) ? qp[lane + 64] : 0.f;

    float s[3];
    bool  val[3];
#pragma unroll
    for (int j = 0; j < 3; j++) {
        const int nn = n + j - 1;
        val[j] = (nn >= 0 && nn < NB);
        float acc = 0.f;
        if (val[j]) {
            const float* kp = k + (size_t)(m + j - 1) * DMODEL + h * 80;
            acc = qv0 * kp[lane] + qv1 * kp[lane + 32];
            if (lane < 16) acc += qv2 * kp[lane + 64];
        }
#pragma unroll
        for (int o = 16; o; o >>= 1) acc += __shfl_xor_sync(0xffffffffu, acc, o);
        s[j] = val[j] ? acc * scale : -1e30f;
    }

    const float mx = fmaxf(s[0], fmaxf(s[1], s[2]));
    float e[3], sum = 0.f;
#pragma unroll
    for (int j = 0; j < 3; j++) {
        e[j] = val[j] ? expf(s[j] - mx) : 0.f;
        sum += e[j];
    }
    const float inv = 1.f / sum;

    float o0 = 0.f, o1 = 0.f, o2 = 0.f;
#pragma unroll
    for (int j = 0; j < 3; j++) {
        if (!val[j]) continue;
        const float p = e[j] * inv;
        const float* vp = v + (size_t)(m + j - 1) * DMODEL + h * 80;
        o0 += p * vp[lane];
        o1 += p * vp[lane + 32];
        if (lane < 16) o2 += p * vp[lane + 64];
    }
    float* cp = ctx + (size_t)m * DMODEL + h * 80;
    cp[lane] = o0;
    cp[lane + 32] = o1;
    if (lane < 16) cp[lane + 64] = o2;
}

// ---------------------------------------------------------------------------
// out[m] = LayerNorm(out[m] + add[m]) * g + b   (row length 640)
// ---------------------------------------------------------------------------
__global__ __launch_bounds__(256) void residual_ln_kernel(
    float* __restrict__ out, const float* __restrict__ add,
    const float* __restrict__ g, const float* __restrict__ b)
{
    const int m = blockIdx.x;
    const int tid = threadIdx.x;
    const int lane = tid & 31, wid = tid >> 5;
    __shared__ float red[8];
    __shared__ float mean_s, rstd_s;

    float v[3];
    float s = 0.f;
#pragma unroll
    for (int i = 0; i < 3; i++) {
        const int d = tid + i * 256;
        float t = 0.f;
        if (d < DMODEL) t = out[(size_t)m * DMODEL + d] + add[(size_t)m * DMODEL + d];
        v[i] = t;
        s += t;
    }
#pragma unroll
    for (int o = 16; o; o >>= 1) s += __shfl_xor_sync(0xffffffffu, s, o);
    if (lane == 0) red[wid] = s;
    __syncthreads();
    if (tid == 0) {
        float t = 0.f;
#pragma unroll
        for (int w = 0; w < 8; w++) t += red[w];
        mean_s = t / (float)DMODEL;
    }
    __syncthreads();
    const float mean = mean_s;

    float vs = 0.f;
#pragma unroll
    for (int i = 0; i < 3; i++) {
        const int d = tid + i * 256;
        if (d < DMODEL) { const float dd = v[i] - mean; vs += dd * dd; }
    }
#pragma unroll
    for (int o = 16; o; o >>= 1) vs += __shfl_xor_sync(0xffffffffu, vs, o);
    __syncthreads();
    if (lane == 0) red[wid] = vs;
    __syncthreads();
    if (tid == 0) {
        float t = 0.f;
#pragma unroll
        for (int w = 0; w < 8; w++) t += red[w];
        rstd_s = rsqrtf(t / (float)DMODEL + 1e-5f);
    }
    __syncthreads();
    const float rstd = rstd_s;
#pragma unroll
    for (int i = 0; i < 3; i++) {
        const int d = tid + i * 256;
        if (d < DMODEL)
            out[(size_t)m * DMODEL + d] = (v[i] - mean) * rstd * g[d] + b[d];
    }
}

// ---------------------------------------------------------------------------
// Host orchestration (graph-capturable: kernel launches only).
// ---------------------------------------------------------------------------
extern "C" void kernel_launch(void* const* d_in, const int* in_sizes, int n_in,
                              void* d_out, int out_size)
{
    const float* x       = (const float*)d_in[0];
    const float* cos_w   = (const float*)d_in[2];
    const float* cos_b   = (const float*)d_in[3];
    const float* attn_w  = (const float*)d_in[4];
    const float* attn_b  = (const float*)d_in[5];
    const float* conv1_w = (const float*)d_in[6];
    const float* conv1_b = (const float*)d_in[7];
    const float* conv2_w = (const float*)d_in[8];
    const float* conv2_b = (const float*)d_in[9];
    const float* Wq      = (const float*)d_in[10];
    const float* Wk      = (const float*)d_in[11];
    const float* Wv      = (const float*)d_in[12];
    const float* Wo      = (const float*)d_in[13];
    const float* ln1_g   = (const float*)d_in[14];
    const float* ln1_b   = (const float*)d_in[15];
    const float* ff1_w   = (const float*)d_in[16];
    const float* ff1_b   = (const float*)d_in[17];
    const float* ff2_w   = (const float*)d_in[18];
    const float* ff2_b   = (const float*)d_in[19];
    const float* ln2_g   = (const float*)d_in[20];
    const float* ln2_b   = (const float*)d_in[21];
    const float* fc_w    = (const float*)d_in[22];
    const float* fc_b    = (const float*)d_in[23];
    const float* cls_w   = (const float*)d_in[24];
    const float* cls_b   = (const float*)d_in[25];
    float* logits = (float*)d_out;

    float *pooled, *obuf, *qb, *kb, *vb, *ctxb, *tmpb, *ffb, *hb;
    cudaGetSymbolAddress((void**)&pooled, g_pooled);
    cudaGetSymbolAddress((void**)&obuf,   g_out);
    cudaGetSymbolAddress((void**)&qb,     g_q);
    cudaGetSymbolAddress((void**)&kb,     g_k);
    cudaGetSymbolAddress((void**)&vb,     g_v);
    cudaGetSymbolAddress((void**)&ctxb,   g_ctx);
    cudaGetSymbolAddress((void**)&tmpb,   g_tmp);
    cudaGetSymbolAddress((void**)&ffb,    g_ff);
    cudaGetSymbolAddress((void**)&hb,     g_h);

    // 1. fused Gram/cos-sim + soft-attention pooling
    pool_sim_kernel<<<MROWS, 256>>>(x, cos_w, cos_b, attn_w, attn_b, pooled, obuf);

    // 2. conv1 (2048 -> 256, k=3) as 3 shift-GEMM taps into out[:, 0:256]
    for (int t = 0; t < 3; t++) {
        const int flags = (t == 0 ? 0 : 2) | (t == 2 ? 1 : 0);  // acc after tap0, relu on last
        gemm128<<<dim3(2, 32), 256>>>(pooled, DIN, t - 1,
                                      conv1_w + t, 3, DIN * 3,
                                      t == 0 ? conv1_b : nullptr,
                                      obuf, DMODEL, MROWS, 256, DIN, flags);
    }
    // 3. conv2 (256 -> 256, k=3) reads out[:,0:256], writes out[:,256:512]
    for (int t = 0; t < 3; t++) {
        const int flags = (t == 0 ? 0 : 2) | (t == 2 ? 1 : 0);
        gemm128<<<dim3(2, 32), 256>>>(obuf, DMODEL, t - 1,
                                      conv2_w + t, 3, 256 * 3,
                                      t == 0 ? conv2_b : nullptr,
                                      obuf + 256, DMODEL, MROWS, 256, 256, flags);
    }

    // 4. transformer layers
    for (int l = 0; l < NLAYER; l++) {
        const size_t wo_off = (size_t)l * DMODEL * DMODEL;
        gemm128<<<dim3(5, 32), 256>>>(obuf, DMODEL, 0, Wq + wo_off, DMODEL, 1,
                                      nullptr, qb, DMODEL, MROWS, DMODEL, DMODEL, 0);
        gemm128<<<dim3(5, 32), 256>>>(obuf, DMODEL, 0, Wk + wo_off, DMODEL, 1,
                                      nullptr, kb, DMODEL, MROWS, DMODEL, DMODEL, 0);
        gemm128<<<dim3(5, 32), 256>>>(obuf, DMODEL, 0, Wv + wo_off, DMODEL, 1,
                                      nullptr, vb, DMODEL, MROWS, DMODEL, DMODEL, 0);

        banded_attn_kernel<<<MROWS, 256>>>(qb, kb, vb, ctxb);  // 4096*8 warps

        gemm128<<<dim3(5, 32), 256>>>(ctxb, DMODEL, 0, Wo + wo_off, DMODEL, 1,
                                      nullptr, tmpb, DMODEL, MROWS, DMODEL, DMODEL, 0);
        residual_ln_kernel<<<MROWS, 256>>>(obuf, tmpb,
                                           ln1_g + l * DMODEL, ln1_b + l * DMODEL);

        gemm128<<<dim3(1, 32), 256>>>(obuf, DMODEL, 0,
                                      ff1_w + (size_t)l * DMODEL * 128, 128, 1,
                                      ff1_b + l * 128,
                                      ffb, 128, MROWS, 128, DMODEL, 1 /*relu*/);
        gemm128<<<dim3(5, 32), 256>>>(ffb, 128, 0,
                                      ff2_w + (size_t)l * 128 * DMODEL, DMODEL, 1,
                                      ff2_b + l * DMODEL,
                                      tmpb, DMODEL, MROWS, DMODEL, 128, 0);
        residual_ln_kernel<<<MROWS, 256>>>(obuf, tmpb,
                                           ln2_g + l * DMODEL, ln2_b + l * DMODEL);
    }

    // 5. head: h = relu(out @ fc + b); logits = h @ cls + b
    gemm128<<<dim3(2, 32), 256>>>(obuf, DMODEL, 0, fc_w, 256, 1, fc_b,
                                  hb, 256, MROWS, 256, DMODEL, 1 /*relu*/);
    gemm128<<<dim3(1, 32), 256>>>(hb, 256, 0, cls_w, 2, 1, cls_b,
                                  logits, 2, MROWS, 2, 256, 0);
}

// round 3
// speedup vs baseline: 2.7119x; 2.7119x over previous
#include <cuda_runtime.h>
#include <cmath>

// ---------------------------------------------------------------------------
// SceneSegCNNTRM round 2: tf32 mma.sync GEMM stack + fused QKV.
// Shapes: B=4, N=1024, W=8, D=2048, H=256, COS_C=128, D_MODEL=640,
//         N_HEADS=8 (d_head=80), FF=128, N_LAYERS=6, M = B*N = 4096.
// ---------------------------------------------------------------------------

#define MROWS   4096
#define NB      1024
#define DIN     2048
#define DMODEL  640
#define NLAYER  6
#define QKVN    1920     // 3 * DMODEL

// Scratch (static device globals -- no allocation allowed)
__device__ __align__(256) float g_pooled[MROWS * DIN];
__device__ __align__(256) float g_out   [MROWS * DMODEL];
__device__ __align__(256) float g_qkv   [MROWS * QKVN];
__device__ __align__(256) float g_wqkv  [NLAYER * DMODEL * QKVN];
__device__ __align__(256) float g_ctx   [MROWS * DMODEL];
__device__ __align__(256) float g_tmp   [MROWS * DMODEL];
__device__ __align__(256) float g_ff    [MROWS * 128];
__device__ __align__(256) float g_h     [MROWS * 256];

// ---------------------------------------------------------------------------
// Pack Wq|Wk|Wv (per layer) into one row-major [640 x 1920] matrix.
// ---------------------------------------------------------------------------
__global__ __launch_bounds__(256) void pack_qkv_kernel(
    const float* __restrict__ Wq, const float* __restrict__ Wk,
    const float* __restrict__ Wv, float* __restrict__ out)
{
    const int i = blockIdx.x * 256 + threadIdx.x;
    if (i >= NLAYER * DMODEL * QKVN) return;
    const int n = i % QKVN;
    const int k = (i / QKVN) % DMODEL;
    const int l = i / (QKVN * DMODEL);
    const float* W = (n < DMODEL) ? Wq : (n < 2 * DMODEL) ? Wk : Wv;
    out[i] = W[(size_t)l * DMODEL * DMODEL + (size_t)k * DMODEL + (n % DMODEL)];
}

// ---------------------------------------------------------------------------
// Kernel 1: per-window Gram matrix + row sums + attn-score dots in one pass;
// cos-sim via quadratic forms -> out[:,512:640]; soft-attn pooled row.
// ---------------------------------------------------------------------------
__global__ __launch_bounds__(256) void pool_sim_kernel(
    const float* __restrict__ x,
    const float* __restrict__ cos_w, const float* __restrict__ cos_b,
    const float* __restrict__ attn_w, const float* __restrict__ attn_b,
    float* __restrict__ pooled, float* __restrict__ outbuf)
{
    const int m   = blockIdx.x;
    const int tid = threadIdx.x;
    const float* xr = x + (size_t)m * 8 * DIN;

    float g12[16], g11[10], g22[10], sw[8], ad[8];
#pragma unroll
    for (int i = 0; i < 16; i++) g12[i] = 0.f;
#pragma unroll
    for (int i = 0; i < 10; i++) { g11[i] = 0.f; g22[i] = 0.f; }
#pragma unroll
    for (int i = 0; i < 8; i++)  { sw[i] = 0.f; ad[i] = 0.f; }

    for (int d = tid; d < DIN; d += 256) {
        float xv[8];
#pragma unroll
        for (int w = 0; w < 8; w++) xv[w] = xr[w * DIN + d];
        const float aw = attn_w[d];
#pragma unroll
        for (int w = 0; w < 8; w++) { sw[w] += xv[w]; ad[w] += xv[w] * aw; }
#pragma unroll
        for (int i = 0; i < 4; i++)
#pragma unroll
            for (int j = 0; j < 4; j++)
                g12[i * 4 + j] += xv[i] * xv[4 + j];
#pragma unroll
        for (int i = 0; i < 4; i++)
#pragma unroll
            for (int j = i; j < 4; j++) {
                const int t = i * (7 - i) / 2 + j;
                g11[t] += xv[i] * xv[j];
                g22[t] += xv[4 + i] * xv[4 + j];
            }
    }

    __shared__ float red[52][8];
    __shared__ float fin[52];
    __shared__ float aprob[8];
    const int lane = tid & 31, wid = tid >> 5;

#define WREDUCE(arr, n, off)                                              \
    _Pragma("unroll")                                                     \
    for (int i = 0; i < n; i++) {                                         \
        float v = arr[i];                                                 \
        _Pragma("unroll")                                                 \
        for (int o = 16; o; o >>= 1) v += __shfl_xor_sync(0xffffffffu, v, o); \
        if (lane == 0) red[off + i][wid] = v;                             \
    }
    WREDUCE(g12, 16, 0)
    WREDUCE(g11, 10, 16)
    WREDUCE(g22, 10, 26)
    WREDUCE(sw,   8, 36)
    WREDUCE(ad,   8, 44)
#undef WREDUCE
    __syncthreads();
    if (tid < 52) {
        float t = 0.f;
#pragma unroll
        for (int w = 0; w < 8; w++) t += red[tid][w];
        fin[tid] = t;
    }
    __syncthreads();

    if (tid == 0) {
        const float ab = attn_b[0];
        float sc[8], mx = -1e30f;
#pragma unroll
        for (int w = 0; w < 8; w++) { sc[w] = fin[44 + w] + ab; mx = fmaxf(mx, sc[w]); }
        float s = 0.f;
#pragma unroll
        for (int w = 0; w < 8; w++) { sc[w] = expf(sc[w] - mx); s += sc[w]; }
        const float inv = 1.f / s;
#pragma unroll
        for (int w = 0; w < 8; w++) aprob[w] = sc[w] * inv;
    }

    if (tid < 128) {
        float cw[4];
#pragma unroll
        for (int w = 0; w < 4; w++) cw[w] = cos_w[tid * 4 + w];
        const float cb = cos_b[tid];
        float d12 = 0.f, q1 = 0.f, q2 = 0.f, cs1 = 0.f, cs2 = 0.f;
#pragma unroll
        for (int i = 0; i < 4; i++)
#pragma unroll
            for (int j = 0; j < 4; j++)
                d12 += cw[i] * cw[j] * fin[i * 4 + j];
#pragma unroll
        for (int i = 0; i < 4; i++)
#pragma unroll
            for (int j = i; j < 4; j++) {
                const int t = i * (7 - i) / 2 + j;
                const float c2 = cw[i] * cw[j] * ((i == j) ? 1.f : 2.f);
                q1 += c2 * fin[16 + t];
                q2 += c2 * fin[26 + t];
            }
#pragma unroll
        for (int w = 0; w < 4; w++) {
            cs1 += cw[w] * fin[36 + w];
            cs2 += cw[w] * fin[40 + w];
        }
        d12 += cb * (cs1 + cs2) + (float)DIN * cb * cb;
        q1  += 2.f * cb * cs1 + (float)DIN * cb * cb;
        q2  += 2.f * cb * cs2 + (float)DIN * cb * cb;
        const float n1 = fmaxf(sqrtf(q1), 1e-8f);
        const float n2 = fmaxf(sqrtf(q2), 1e-8f);
        outbuf[(size_t)m * DMODEL + 512 + tid] = d12 / (n1 * n2);
    }
    __syncthreads();

    float a[8];
#pragma unroll
    for (int w = 0; w < 8; w++) a[w] = aprob[w];
    for (int d = tid; d < DIN; d += 256) {
        float p = 0.f;
#pragma unroll
        for (int w = 0; w < 8; w++) p += a[w] * xr[w * DIN + d];
        pooled[(size_t)m * DIN + d] = p;
    }
}

// ---------------------------------------------------------------------------
// tf32 tensor-core GEMM: C[M,N] (+)= A[M,K] * B[K,N]
//  - BMxBN = BMx128, BK=16, 256 threads, 8 warps as 2x4, mma.m16n8k8.tf32
//  - shift: A row offset (conv tap) masked per NB-row batch
//  - generic B strides (ldbK, ldbN); float4 fast path when ldbN==1
//  - flags: bit0 = relu, bit1 = accumulate into C
//  Requires: M % BM == 0, K % 16 == 0.
// ---------------------------------------------------------------------------
__device__ __forceinline__ float to_tf32(float x) {
    asm("cvt.rna.tf32.f32 %0, %0;" : "+f"(x));
    return x;
}

template<int BM>
__global__ __launch_bounds__(256) void gemm_tf32(
    const float* __restrict__ A, int lda, int shift,
    const float* __restrict__ B, int ldbK, int ldbN,
    const float* __restrict__ bias,
    float* __restrict__ C, int ldc,
    int M, int N, int K, int flags)
{
    constexpr int MT = BM / 32;              // m16 tiles per warp
    constexpr int RA = BM / 64;              // float4 A-loads per thread
    __shared__ float As[2][16][BM + 4];
    __shared__ float Bs[2][16][128 + 4];

    const int tid = threadIdx.x;
    const int bm = blockIdx.y * BM;
    const int bn = blockIdx.x * 128;
    const int w = tid >> 5, lane = tid & 31;
    const int g = lane >> 2, tg = lane & 3;
    const int wm = (w >> 2) * (BM / 2);
    const int wn = (w & 3) * 32;
    const bool vecB = (ldbN == 1);

    float acc[MT][4][4];
#pragma unroll
    for (int i = 0; i < MT; i++)
#pragma unroll
        for (int j = 0; j < 4; j++)
#pragma unroll
            for (int r = 0; r < 4; r++) acc[i][j][r] = 0.f;

    float4 ra[RA];
    float4 rb4[2];
    float  rbs[8];

    auto loadA = [&](int k0) {
#pragma unroll
        for (int r = 0; r < RA; r++) {
            const int idx = tid + r * 256;
            const int row = idx >> 2, cg = (idx & 3) << 2;
            const int gm = bm + row;
            float4 v = make_float4(0.f, 0.f, 0.f, 0.f);
            if ((unsigned)((gm & (NB - 1)) + shift) < (unsigned)NB)
                v = *reinterpret_cast<const float4*>(A + (size_t)(gm + shift) * lda + k0 + cg);
            ra[r] = v;
        }
    };
    auto storeA = [&](int st) {
#pragma unroll
        for (int r = 0; r < RA; r++) {
            const int idx = tid + r * 256;
            const int row = idx >> 2, cg = (idx & 3) << 2;
            As[st][cg + 0][row] = to_tf32(ra[r].x);
            As[st][cg + 1][row] = to_tf32(ra[r].y);
            As[st][cg + 2][row] = to_tf32(ra[r].z);
            As[st][cg + 3][row] = to_tf32(ra[r].w);
        }
    };
    auto loadB = [&](int k0) {
        if (vecB) {
#pragma unroll
            for (int r = 0; r < 2; r++) {
                const int idx = tid + r * 256;
                const int kk = idx >> 5, nn = (idx & 31) << 2;
                const int gn = bn + nn;
                const float* p = B + (size_t)(k0 + kk) * ldbK + gn;
                float4 v = make_float4(0.f, 0.f, 0.f, 0.f);
                if (gn + 3 < N) v = *reinterpret_cast<const float4*>(p);
                else {
                    if (gn + 0 < N) v.x = p[0];
                    if (gn + 1 < N) v.y = p[1];
                    if (gn + 2 < N) v.z = p[2];
                }
                rb4[r] = v;
            }
        } else {
#pragma unroll
            for (int r = 0; r < 8; r++) {
                const int idx = tid + r * 256;
                const int kk = idx >> 7, nn = idx & 127;
                const int gn = bn + nn;
                rbs[r] = (gn < N) ? B[(size_t)(k0 + kk) * ldbK + (size_t)gn * ldbN] : 0.f;
            }
        }
    };
    auto storeB = [&](int st) {
        if (vecB) {
#pragma unroll
            for (int r = 0; r < 2; r++) {
                const int idx = tid + r * 256;
                const int kk = idx >> 5, nn = (idx & 31) << 2;
                Bs[st][kk][nn + 0] = to_tf32(rb4[r].x);
                Bs[st][kk][nn + 1] = to_tf32(rb4[r].y);
                Bs[st][kk][nn + 2] = to_tf32(rb4[r].z);
                Bs[st][kk][nn + 3] = to_tf32(rb4[r].w);
            }
        } else {
#pragma unroll
            for (int r = 0; r < 8; r++) {
                const int idx = tid + r * 256;
                const int kk = idx >> 7, nn = idx & 127;
                Bs[st][kk][nn] = to_tf32(rbs[r]);
            }
        }
    };

    loadA(0); loadB(0);
    storeA(0); storeB(0);
    __syncthreads();

    int st = 0;
    for (int k0 = 0; k0 < K; k0 += 16) {
        const bool more = (k0 + 16) < K;
        if (more) { loadA(k0 + 16); loadB(k0 + 16); }

#pragma unroll
        for (int kb = 0; kb < 2; kb++) {
            unsigned a[MT][4], b[4][2];
            const int kr = kb * 8;
#pragma unroll
            for (int mi = 0; mi < MT; mi++) {
                const int m0 = wm + mi * 16 + g;
                a[mi][0] = __float_as_uint(As[st][kr + tg][m0]);
                a[mi][1] = __float_as_uint(As[st][kr + tg][m0 + 8]);
                a[mi][2] = __float_as_uint(As[st][kr + tg + 4][m0]);
                a[mi][3] = __float_as_uint(As[st][kr + tg + 4][m0 + 8]);
            }
#pragma unroll
            for (int nj = 0; nj < 4; nj++) {
                const int n0 = wn + nj * 8 + g;
                b[nj][0] = __float_as_uint(Bs[st][kr + tg][n0]);
                b[nj][1] = __float_as_uint(Bs[st][kr + tg + 4][n0]);
            }
#pragma unroll
            for (int mi = 0; mi < MT; mi++)
#pragma unroll
                for (int nj = 0; nj < 4; nj++)
                    asm volatile(
                        "mma.sync.aligned.m16n8k8.row.col.f32.tf32.tf32.f32 "
                        "{%0,%1,%2,%3}, {%4,%5,%6,%7}, {%8,%9}, {%0,%1,%2,%3};\n"
                        : "+f"(acc[mi][nj][0]), "+f"(acc[mi][nj][1]),
                          "+f"(acc[mi][nj][2]), "+f"(acc[mi][nj][3])
                        : "r"(a[mi][0]), "r"(a[mi][1]), "r"(a[mi][2]), "r"(a[mi][3]),
                          "r"(b[nj][0]), "r"(b[nj][1]));
        }

        if (more) {
            storeA(st ^ 1); storeB(st ^ 1);
            __syncthreads();
            st ^= 1;
        }
    }

    // epilogue
#pragma unroll
    for (int mi = 0; mi < MT; mi++) {
        const int r0 = bm + wm + mi * 16 + g;
#pragma unroll
        for (int nj = 0; nj < 4; nj++) {
            const int c0 = bn + wn + nj * 8 + tg * 2;
#pragma unroll
            for (int hh = 0; hh < 2; hh++) {
                const int row = r0 + hh * 8;
                float* crow = C + (size_t)row * ldc;
#pragma unroll
                for (int cc = 0; cc < 2; cc++) {
                    const int col = c0 + cc;
                    if (col >= N) continue;
                    float v = acc[mi][nj][hh * 2 + cc];
                    if (bias) v += bias[col];
                    if (flags & 2) v += crow[col];
                    if (flags & 1) v = fmaxf(v, 0.f);
                    crow[col] = v;
                }
            }
        }
    }
}

// ---------------------------------------------------------------------------
// Banded local attention over packed qkv rows (stride 1920).
// One warp per (token, head); d_head = 80.
// ---------------------------------------------------------------------------
__global__ __launch_bounds__(256) void banded_attn_kernel(
    const float* __restrict__ qkv, float* __restrict__ ctx)
{
    const int gw   = (blockIdx.x * 256 + threadIdx.x) >> 5;
    const int lane = threadIdx.x & 31;
    if (gw >= MROWS * 8) return;
    const int m = gw >> 3;
    const int h = gw & 7;
    const int n = m & (NB - 1);
    const float scale = 0.11180339887498949f;  // 1/sqrt(80)

    const float* qp = qkv + (size_t)m * QKVN + h * 80;
    const float qv0 = qp[lane], qv1 = qp[lane + 32];
    const float qv2 = (lane < 16) ? qp[lane + 64] : 0.f;

    float s[3];
    bool  val[3];
#pragma unroll
    for (int j = 0; j < 3; j++) {
        const int nn = n + j - 1;
        val[j] = (nn >= 0 && nn < NB);
        float acc = 0.f;
        if (val[j]) {
            const float* kp = qkv + (size_t)(m + j - 1) * QKVN + DMODEL + h * 80;
            acc = qv0 * kp[lane] + qv1 * kp[lane + 32];
            if (lane < 16) acc += qv2 * kp[lane + 64];
        }
#pragma unroll
        for (int o = 16; o; o >>= 1) acc += __shfl_xor_sync(0xffffffffu, acc, o);
        s[j] = val[j] ? acc * scale : -1e30f;
    }

    const float mx = fmaxf(s[0], fmaxf(s[1], s[2]));
    float e[3], sum = 0.f;
#pragma unroll
    for (int j = 0; j < 3; j++) {
        e[j] = val[j] ? expf(s[j] - mx) : 0.f;
        sum += e[j];
    }
    const float inv = 1.f / sum;

    float o0 = 0.f, o1 = 0.f, o2 = 0.f;
#pragma unroll
    for (int j = 0; j < 3; j++) {
        if (!val[j]) continue;
        const float p = e[j] * inv;
        const float* vp = qkv + (size_t)(m + j - 1) * QKVN + 2 * DMODEL + h * 80;
        o0 += p * vp[lane];
        o1 += p * vp[lane + 32];
        if (lane < 16) o2 += p * vp[lane + 64];
    }
    float* cp = ctx + (size_t)m * DMODEL + h * 80;
    cp[lane] = o0;
    cp[lane + 32] = o1;
    if (lane < 16) cp[lane + 64] = o2;
}

// ---------------------------------------------------------------------------
// out[m] = LayerNorm(out[m] + add[m]) * g + b   (row length 640)
// ---------------------------------------------------------------------------
__global__ __launch_bounds__(256) void residual_ln_kernel(
    float* __restrict__ out, const float* __restrict__ add,
    const float* __restrict__ g, const float* __restrict__ b)
{
    const int m = blockIdx.x;
    const int tid = threadIdx.x;
    const int lane = tid & 31, wid = tid >> 5;
    __shared__ float red[8];
    __shared__ float mean_s, rstd_s;

    float v[3];
    float s = 0.f;
#pragma unroll
    for (int i = 0; i < 3; i++) {
        const int d = tid + i * 256;
        float t = 0.f;
        if (d < DMODEL) t = out[(size_t)m * DMODEL + d] + add[(size_t)m * DMODEL + d];
        v[i] = t;
        s += t;
    }
#pragma unroll
    for (int o = 16; o; o >>= 1) s += __shfl_xor_sync(0xffffffffu, s, o);
    if (lane == 0) red[wid] = s;
    __syncthreads();
    if (tid == 0) {
        float t = 0.f;
#pragma unroll
        for (int w = 0; w < 8; w++) t += red[w];
        mean_s = t / (float)DMODEL;
    }
    __syncthreads();
    const float mean = mean_s;

    float vs = 0.f;
#pragma unroll
    for (int i = 0; i < 3; i++) {
        const int d = tid + i * 256;
        if (d < DMODEL) { const float dd = v[i] - mean; vs += dd * dd; }
    }
#pragma unroll
    for (int o = 16; o; o >>= 1) vs += __shfl_xor_sync(0xffffffffu, vs, o);
    __syncthreads();
    if (lane == 0) red[wid] = vs;
    __syncthreads();
    if (tid == 0) {
        float t = 0.f;
#pragma unroll
        for (int w = 0; w < 8; w++) t += red[w];
        rstd_s = rsqrtf(t / (float)DMODEL + 1e-5f);
    }
    __syncthreads();
    const float rstd = rstd_s;
#pragma unroll
    for (int i = 0; i < 3; i++) {
        const int d = tid + i * 256;
        if (d < DMODEL)
            out[(size_t)m * DMODEL + d] = (v[i] - mean) * rstd * g[d] + b[d];
    }
}

// ---------------------------------------------------------------------------
// Host orchestration (graph-capturable: kernel launches only).
// ---------------------------------------------------------------------------
extern "C" void kernel_launch(void* const* d_in, const int* in_sizes, int n_in,
                              void* d_out, int out_size)
{
    const float* x       = (const float*)d_in[0];
    const float* cos_w   = (const float*)d_in[2];
    const float* cos_b   = (const float*)d_in[3];
    const float* attn_w  = (const float*)d_in[4];
    const float* attn_b  = (const float*)d_in[5];
    const float* conv1_w = (const float*)d_in[6];
    const float* conv1_b = (const float*)d_in[7];
    const float* conv2_w = (const float*)d_in[8];
    const float* conv2_b = (const float*)d_in[9];
    const float* Wq      = (const float*)d_in[10];
    const float* Wk      = (const float*)d_in[11];
    const float* Wv      = (const float*)d_in[12];
    const float* Wo      = (const float*)d_in[13];
    const float* ln1_g   = (const float*)d_in[14];
    const float* ln1_b   = (const float*)d_in[15];
    const float* ff1_w   = (const float*)d_in[16];
    const float* ff1_b   = (const float*)d_in[17];
    const float* ff2_w   = (const float*)d_in[18];
    const float* ff2_b   = (const float*)d_in[19];
    const float* ln2_g   = (const float*)d_in[20];
    const float* ln2_b   = (const float*)d_in[21];
    const float* fc_w    = (const float*)d_in[22];
    const float* fc_b    = (const float*)d_in[23];
    const float* cls_w   = (const float*)d_in[24];
    const float* cls_b   = (const float*)d_in[25];
    float* logits = (float*)d_out;

    float *pooled, *obuf, *qkvb, *wqkv, *ctxb, *tmpb, *ffb, *hb;
    cudaGetSymbolAddress((void**)&pooled, g_pooled);
    cudaGetSymbolAddress((void**)&obuf,   g_out);
    cudaGetSymbolAddress((void**)&qkvb,   g_qkv);
    cudaGetSymbolAddress((void**)&wqkv,   g_wqkv);
    cudaGetSymbolAddress((void**)&ctxb,   g_ctx);
    cudaGetSymbolAddress((void**)&tmpb,   g_tmp);
    cudaGetSymbolAddress((void**)&ffb,    g_ff);
    cudaGetSymbolAddress((void**)&hb,     g_h);

    // 0. pack QKV weights for all layers
    {
        const int tot = NLAYER * DMODEL * QKVN;
        pack_qkv_kernel<<<(tot + 255) / 256, 256>>>(Wq, Wk, Wv, wqkv);
    }

    // 1. fused Gram/cos-sim + soft-attention pooling
    pool_sim_kernel<<<MROWS, 256>>>(x, cos_w, cos_b, attn_w, attn_b, pooled, obuf);

    // 2. conv1 (2048 -> 256, k=3) as 3 shift-GEMM taps into out[:, 0:256]
    for (int t = 0; t < 3; t++) {
        const int flags = (t == 0 ? 0 : 2) | (t == 2 ? 1 : 0);
        gemm_tf32<64><<<dim3(2, 64), 256>>>(pooled, DIN, t - 1,
                                            conv1_w + t, 3, DIN * 3,
                                            t == 0 ? conv1_b : nullptr,
                                            obuf, DMODEL, MROWS, 256, DIN, flags);
    }
    // 3. conv2 (256 -> 256, k=3) reads out[:,0:256], writes out[:,256:512]
    for (int t = 0; t < 3; t++) {
        const int flags = (t == 0 ? 0 : 2) | (t == 2 ? 1 : 0);
        gemm_tf32<64><<<dim3(2, 64), 256>>>(obuf, DMODEL, t - 1,
                                            conv2_w + t, 3, 256 * 3,
                                            t == 0 ? conv2_b : nullptr,
                                            obuf + 256, DMODEL, MROWS, 256, 256, flags);
    }

    // 4. transformer layers
    for (int l = 0; l < NLAYER; l++) {
        // fused QKV projection: [4096 x 640] @ [640 x 1920]
        gemm_tf32<128><<<dim3(15, 32), 256>>>(obuf, DMODEL, 0,
                                              wqkv + (size_t)l * DMODEL * QKVN, QKVN, 1,
                                              nullptr, qkvb, QKVN,
                                              MROWS, QKVN, DMODEL, 0);

        banded_attn_kernel<<<MROWS, 256>>>(qkvb, ctxb);

        gemm_tf32<64><<<dim3(5, 64), 256>>>(ctxb, DMODEL, 0,
                                            Wo + (size_t)l * DMODEL * DMODEL, DMODEL, 1,
                                            nullptr, tmpb, DMODEL,
                                            MROWS, DMODEL, DMODEL, 0);
        residual_ln_kernel<<<MROWS, 256>>>(obuf, tmpb,
                                           ln1_g + l * DMODEL, ln1_b + l * DMODEL);

        gemm_tf32<64><<<dim3(1, 64), 256>>>(obuf, DMODEL, 0,
                                            ff1_w + (size_t)l * DMODEL * 128, 128, 1,
                                            ff1_b + l * 128,
                                            ffb, 128, MROWS, 128, DMODEL, 1 /*relu*/);
        gemm_tf32<64><<<dim3(5, 64), 256>>>(ffb, 128, 0,
                                            ff2_w + (size_t)l * 128 * DMODEL, DMODEL, 1,
                                            ff2_b + l * DMODEL,
                                            tmpb, DMODEL, MROWS, DMODEL, 128, 0);
        residual_ln_kernel<<<MROWS, 256>>>(obuf, tmpb,
                                           ln2_g + l * DMODEL, ln2_b + l * DMODEL);
    }

    // 5. head: h = relu(out @ fc + b); logits = h @ cls + b
    gemm_tf32<64><<<dim3(2, 64), 256>>>(obuf, DMODEL, 0, fc_w, 256, 1, fc_b,
                                        hb, 256, MROWS, 256, DMODEL, 1 /*relu*/);
    gemm_tf32<128><<<dim3(1, 32), 256>>>(hb, 256, 0, cls_w, 2, 1, cls_b,
                                         logits, 2, MROWS, 2, 256, 0);
}